// round 4
// baseline (speedup 1.0000x reference)
#include <cuda_runtime.h>
#include <stdint.h>
#include <math.h>

// ============================================================================
// RadialMasking — bit-exact JAX reproduction (reference = XLA:CPU + glibc).
//  R4 change: atan2 = fdlibm/musl flt-32 atan2f/atanf port (glibc <= 2.39),
//  every op pinned to f32 RN intrinsics (no FMA, immune to fast-math).
//  Evidence: libdevice ~4 flips (R1=R3), CR-f32 ~5 flips (R2) -> third impl
//  within ~1 ulp of both == classic fdlibm.
// ============================================================================

#define NMAX 1600000
#define NB 8

__device__ unsigned int  g_histall[8 + NB * 4][65536]; // [0..7] coarse, [8+b*4+s] fine
__device__ float         g_dist[NMAX];
__device__ unsigned char g_keep1[NMAX];
__device__ unsigned int  g_selbits[96];
__device__ unsigned int  g_m[NB];
__device__ int           g_bucket[NB][4];
__device__ int           g_rankin[NB][4];
__device__ float         g_w[NB][4];       // lw(q1), hw(q1), lw(q2), hw(q2)
__device__ float         g_selval[NB][4];  // sorted[low(q1)], sorted[high(q1)], low(q2), high(q2)
__device__ float         g_q[NB][2];

// ---------------- fdlibm flt-32 atanf / atan2f ------------------------------
__device__ __forceinline__ float fd_atanf(float x) {
    const float atanhi[4] = {4.6364760399e-01f, 7.8539812565e-01f,
                             9.8279368877e-01f, 1.5707962513e+00f};
    const float atanlo[4] = {5.0121582440e-09f, 3.7748947079e-08f,
                             3.4473217170e-08f, 7.5497894159e-08f};
    const float aT0 =  3.3333328366e-01f;
    const float aT1 = -1.9999158382e-01f;
    const float aT2 =  1.4253635705e-01f;
    const float aT3 = -1.0648017377e-01f;
    const float aT4 =  6.1687607318e-02f;
    unsigned ix = __float_as_uint(x);
    unsigned sign = ix >> 31;
    ix &= 0x7fffffffu;
    int id;
    if (ix >= 0x4c800000u) {                 // |x| >= 2^26
        float z = atanhi[3];                 // (+0x1p-120 is a no-op in f32)
        return sign ? -z : z;
    }
    if (ix < 0x3ee00000u) {                  // |x| < 0.4375
        if (ix < 0x39800000u) return x;      // |x| < 2^-12
        id = -1;
    } else {
        x = fabsf(x);
        if (ix < 0x3f980000u) {              // |x| < 1.1875
            if (ix < 0x3f300000u) {          // 7/16 <= |x| < 11/16
                id = 0;
                x = __fdiv_rn(__fsub_rn(__fadd_rn(x, x), 1.0f), __fadd_rn(2.0f, x));
            } else {                         // 11/16 <= |x| < 19/16
                id = 1;
                x = __fdiv_rn(__fsub_rn(x, 1.0f), __fadd_rn(x, 1.0f));
            }
        } else {
            if (ix < 0x401c0000u) {          // |x| < 2.4375
                id = 2;
                x = __fdiv_rn(__fsub_rn(x, 1.5f), __fadd_rn(1.0f, __fmul_rn(1.5f, x)));
            } else {                         // 2.4375 <= |x| < 2^26
                id = 3;
                x = __fdiv_rn(-1.0f, x);
            }
        }
    }
    float z = __fmul_rn(x, x);
    float w = __fmul_rn(z, z);
    float s1 = __fmul_rn(z, __fadd_rn(aT0, __fmul_rn(w, __fadd_rn(aT2, __fmul_rn(w, aT4)))));
    float s2 = __fmul_rn(w, __fadd_rn(aT1, __fmul_rn(w, aT3)));
    if (id < 0)
        return __fsub_rn(x, __fmul_rn(x, __fadd_rn(s1, s2)));
    z = __fsub_rn(atanhi[id],
                  __fsub_rn(__fsub_rn(__fmul_rn(x, __fadd_rn(s1, s2)), atanlo[id]), x));
    return sign ? -z : z;
}

__device__ __forceinline__ float fd_atan2f(float y, float x) {
    const float pi    = 3.1415927410e+00f;   // 0x40490fdb
    const float pi_lo = -8.7422776573e-08f;  // 0xb3bbbd2e
    const float pio2  = 1.5707963705e+00f;   // 0x3fc90fdb = pi/2 in f32
    unsigned hx = __float_as_uint(x), hy = __float_as_uint(y);
    if (hx == 0x3f800000u) return fd_atanf(y);        // x == +1.0
    unsigned m = ((hy >> 31) & 1u) | ((hx >> 30) & 2u);
    unsigned ix = hx & 0x7fffffffu, iy = hy & 0x7fffffffu;
    if (iy == 0u) {                                    // y == +-0
        switch (m) {
        case 0: case 1: return y;
        case 2: return pi;
        default: return -pi;
        }
    }
    if (ix == 0u) return (m & 1u) ? -pio2 : pio2;      // x == +-0
    // (inf cases impossible for this data)
    if (ix + (26u << 23) < iy) return (m & 1u) ? -pio2 : pio2;  // |y/x| > 2^26
    float z;
    if ((m & 2u) && iy + (26u << 23) < ix)             // |y/x| < 2^-26, x<0
        z = 0.0f;
    else
        z = fd_atanf(fabsf(__fdiv_rn(y, x)));
    switch (m) {
    case 0: return z;
    case 1: return -z;
    case 2: return __fsub_rn(pi, __fsub_rn(z, pi_lo));
    default: return __fsub_rn(__fsub_rn(z, pi_lo), pi);
    }
}

// ---------------- Threefry-2x32 (JAX threefry2x32_p, 20 rounds) -------------
__device__ __forceinline__ void tf_round(unsigned& x0, unsigned& x1, int r) {
    x0 += x1;
    x1 = __funnelshift_l(x1, x1, r);
    x1 ^= x0;
}

__device__ __forceinline__ uint2 tf2x32(unsigned k0, unsigned k1, unsigned x0, unsigned x1) {
    unsigned k2 = k0 ^ k1 ^ 0x1BD11BDAu;
    x0 += k0; x1 += k1;
    tf_round(x0, x1, 13); tf_round(x0, x1, 15); tf_round(x0, x1, 26); tf_round(x0, x1, 6);
    x0 += k1; x1 += k2 + 1u;
    tf_round(x0, x1, 17); tf_round(x0, x1, 29); tf_round(x0, x1, 16); tf_round(x0, x1, 24);
    x0 += k2; x1 += k0 + 2u;
    tf_round(x0, x1, 13); tf_round(x0, x1, 15); tf_round(x0, x1, 26); tf_round(x0, x1, 6);
    x0 += k0; x1 += k1 + 3u;
    tf_round(x0, x1, 17); tf_round(x0, x1, 29); tf_round(x0, x1, 16); tf_round(x0, x1, 24);
    x0 += k1; x1 += k2 + 4u;
    tf_round(x0, x1, 13); tf_round(x0, x1, 15); tf_round(x0, x1, 26); tf_round(x0, x1, 6);
    x0 += k2; x1 += k0 + 5u;
    return make_uint2(x0, x1);
}

// jax.random.uniform bit path: f32 in [0,1)
__device__ __forceinline__ float bits_to_unit(unsigned bits) {
    return __fadd_rn(__uint_as_float((bits >> 9) | 0x3f800000u), -1.0f);
}

// ---------------- k_zero ----------------------------------------------------
__global__ void k_zero() {
    unsigned total = (8u + NB * 4u) * 65536u;
    unsigned* p = &g_histall[0][0];
    for (unsigned i = blockIdx.x * blockDim.x + threadIdx.x; i < total;
         i += gridDim.x * blockDim.x)
        p[i] = 0u;
}

// ---------------- k_selgroups -----------------------------------------------
// key(42) = (0,42); partitionable split: kg = TF(key,(0,0)); sel bits over 8x360
__global__ void k_selgroups() {
    int t = threadIdx.x;
    if (t < 96) g_selbits[t] = 0u;
    __syncthreads();
    uint2 kg = tf2x32(0u, 42u, 0u, 0u);
    for (int i = t; i < NB * 360; i += blockDim.x) {
        uint2 r = tf2x32(kg.x, kg.y, 0u, (unsigned)i);
        float u = bits_to_unit(r.x ^ r.y);
        if (u < 0.2f) atomicOr(&g_selbits[i >> 5], 1u << (i & 31));
    }
}

// ---------------- k_stage1 --------------------------------------------------
__global__ void k_stage1(const int4* __restrict__ coords, int N, int npb) {
    int p = blockIdx.x * blockDim.x + threadIdx.x;
    if (p >= N) return;
    int4 c = coords[p];  // (b, z, y, x)
    float xm = __fadd_rn(__fmul_rn((float)c.w, 0.1f), -70.0f);
    float ym = __fadd_rn(__fmul_rn((float)c.z, 0.1f), -40.0f);
    // fdlibm atan2f (glibc flt-32), then f32 degrees / mod / trunc.
    float th = fd_atan2f(ym, xm);
    float td = __fmul_rn(th, 57.29577951308232f);    // jnp.degrees constant
    float tm = (td < 0.0f) ? __fadd_rn(td, 360.0f) : td;  // jnp.mod for |x|<=360
    int grp = (int)tm;                               // f32->s32 truncation
    grp = min(max(grp, 0), 359);
    int b = p / npb;
    int bitidx = b * 360 + grp;
    unsigned keep1 = (g_selbits[bitidx >> 5] >> (bitidx & 31)) & 1u;
    float d2 = __fadd_rn(__fmul_rn(xm, xm), __fmul_rn(ym, ym));
    float dist = __fsqrt_rn(d2);
    g_dist[p] = dist;
    g_keep1[p] = (unsigned char)keep1;
    if (keep1) atomicAdd(&g_histall[b][__float_as_uint(dist) >> 16], 1u);
}

// ---------------- k_coarse --------------------------------------------------
__global__ void k_coarse() {
    int b = blockIdx.x;
    const unsigned* hist = g_histall[b];
    __shared__ unsigned sp[1024];
    __shared__ int s_r[4];
    __shared__ unsigned s_m;
    unsigned part = 0;
    int base = threadIdx.x * 64;
#pragma unroll 8
    for (int i = 0; i < 64; i++) part += hist[base + i];
    sp[threadIdx.x] = part;
    __syncthreads();
    for (int off = 1; off < 1024; off <<= 1) {
        unsigned v = (threadIdx.x >= off) ? sp[threadIdx.x - off] : 0u;
        __syncthreads();
        sp[threadIdx.x] += v;
        __syncthreads();
    }
    if (threadIdx.x == 0) {
        unsigned m = sp[1023];
        s_m = m;
        g_m[b] = m;
        // JAX nanquantile (squash_nans, method='linear'), all f32:
        float mf  = (float)m;
        float cm1 = __fsub_rn(mf, 1.0f);
        const float qv[2] = {0.33f, 0.67f};
        for (int j = 0; j < 2; j++) {
            float qidx = __fmul_rn(qv[j], cm1);
            float lo = floorf(qidx), hi = ceilf(qidx);
            float hw = __fsub_rn(qidx, lo);
            float lw = __fsub_rn(1.0f, hw);
            float loc = fmaxf(0.0f, fminf(lo, cm1));
            float hic = fmaxf(0.0f, fminf(hi, cm1));
            s_r[j * 2]     = (int)loc;
            s_r[j * 2 + 1] = (int)hic;
            g_w[b][j * 2]     = lw;
            g_w[b][j * 2 + 1] = hw;
        }
    }
    __syncthreads();
    if (threadIdx.x < 4) {
        int s = threadIdx.x;
        if (s_m == 0) {
            g_bucket[b][s] = -1;
            g_rankin[b][s] = 0;
        } else {
            unsigned r = (unsigned)s_r[s];
            int lo = 0, hi = 1023;
            while (lo < hi) {
                int mid = (lo + hi) >> 1;
                if (sp[mid] > r) hi = mid; else lo = mid + 1;
            }
            unsigned cum = (lo == 0) ? 0u : sp[lo - 1];
            int bin = lo * 64;
            while (cum + hist[bin] <= r) { cum += hist[bin]; bin++; }
            g_bucket[b][s] = bin;
            g_rankin[b][s] = (int)(r - cum);
        }
    }
}

// ---------------- k_finecnt -------------------------------------------------
__global__ void k_finecnt(int N, int npb) {
    int p = blockIdx.x * blockDim.x + threadIdx.x;
    if (p >= N) return;
    if (!g_keep1[p]) return;
    unsigned bits = __float_as_uint(g_dist[p]);
    int b = p / npb;
    int coarse = (int)(bits >> 16);
    unsigned fbin = bits & 0xFFFFu;
#pragma unroll
    for (int s = 0; s < 4; s++)
        if (g_bucket[b][s] == coarse)
            atomicAdd(&g_histall[8 + b * 4 + s][fbin], 1u);
}

// ---------------- k_finescan ------------------------------------------------
__global__ void k_finescan() {
    int b = blockIdx.x >> 2, s = blockIdx.x & 3;
    int bucket = g_bucket[b][s];
    if (bucket < 0) {
        if (threadIdx.x == 0) g_selval[b][s] = __int_as_float(0x7fc00000);
        return;
    }
    const unsigned* hist = g_histall[8 + b * 4 + s];
    __shared__ unsigned sp[1024];
    unsigned part = 0;
    int base = threadIdx.x * 64;
#pragma unroll 8
    for (int i = 0; i < 64; i++) part += hist[base + i];
    sp[threadIdx.x] = part;
    __syncthreads();
    for (int off = 1; off < 1024; off <<= 1) {
        unsigned v = (threadIdx.x >= off) ? sp[threadIdx.x - off] : 0u;
        __syncthreads();
        sp[threadIdx.x] += v;
        __syncthreads();
    }
    if (threadIdx.x == 0) {
        unsigned r = (unsigned)g_rankin[b][s];
        int lo = 0, hi = 1023;
        while (lo < hi) {
            int mid = (lo + hi) >> 1;
            if (sp[mid] > r) hi = mid; else lo = mid + 1;
        }
        unsigned cum = (lo == 0) ? 0u : sp[lo - 1];
        int bin = lo * 64;
        while (cum + hist[bin] <= r) { cum += hist[bin]; bin++; }
        g_selval[b][s] = __uint_as_float(((unsigned)bucket << 16) | (unsigned)bin);
    }
}

// ---------------- k_qcalc ---------------------------------------------------
__global__ void k_qcalc() {
    int t = threadIdx.x;
    if (t >= NB * 2) return;
    int b = t >> 1, j = t & 1;
    float q;
    if (g_m[b] == 0) {
        q = __int_as_float(0x7fc00000);
    } else {
        q = __fadd_rn(__fmul_rn(g_selval[b][2 * j],     g_w[b][2 * j]),
                      __fmul_rn(g_selval[b][2 * j + 1], g_w[b][2 * j + 1]));
    }
    g_q[b][j] = q;
}

// ---------------- k_final ---------------------------------------------------
// 16 lanes per voxel: lane0 computes keep (one Threefry per voxel), shuffle
// broadcasts kf; kept rows copy features, masked rows store zeros (no load).
__global__ void k_final(const float4* __restrict__ feat, float* __restrict__ out_keep,
                        float4* __restrict__ out_feat, int N, int npb) {
    long long idx = (long long)blockIdx.x * blockDim.x + threadIdx.x;
    int v = (int)(idx >> 4);
    int lane = (int)(idx & 15);
    bool active = (v < N);
    int vv = active ? v : (N - 1);
    float kf = 0.0f;
    if (lane == 0) {
        int b = vv / npb;
        float dist = g_dist[vv];
        float q1 = g_q[b][0], q2 = g_q[b][1];
        // jnp.where(dist<q1, 0.48, where(dist<q2, 0.8, 0.95)); NaN q -> 0.95
        float prob = (dist < q1) ? 0.48f : ((dist < q2) ? 0.8f : 0.95f);
        // kv = TF(key,(0,1)) (fold-like split); u = unit uniform at flat index vv
        uint2 kv = tf2x32(0u, 42u, 0u, 1u);
        uint2 r = tf2x32(kv.x, kv.y, 0u, (unsigned)vv);
        float u = bits_to_unit(r.x ^ r.y);
        bool keep = (g_keep1[vv] != 0) && (u >= prob);
        kf = keep ? 1.0f : 0.0f;
        if (active && out_keep != nullptr) out_keep[vv] = kf;
    }
    int lw = threadIdx.x & 31;
    kf = __shfl_sync(0xffffffffu, kf, lw & ~15);
    if (active && out_feat != nullptr) {
        size_t off = (size_t)vv * 16 + lane;
        if (kf != 0.0f) {
            out_feat[off] = feat[off];
        } else {
            out_feat[off] = make_float4(0.0f, 0.0f, 0.0f, 0.0f);
        }
    }
}

// ---------------- launcher --------------------------------------------------
extern "C" void kernel_launch(void* const* d_in, const int* in_sizes, int n_in,
                              void* d_out, int out_size) {
    // identify inputs by size: coords = 4N ints, features = 64N floats
    int i_coords = 0, i_feat = 1;
    if (n_in >= 2 && in_sizes[0] > in_sizes[1]) { i_coords = 1; i_feat = 0; }
    const int4*   coords = (const int4*)d_in[i_coords];
    const float4* feat   = (const float4*)d_in[i_feat];
    int N = in_sizes[i_coords] / 4;
    int npb = N / NB;

    float*  out      = (float*)d_out;
    float*  out_keep = nullptr;
    float4* out_feat = nullptr;
    long long os = (long long)out_size;
    if (os >= (long long)N * 65) {        // [keep f32 x N][features f32 x 64N]
        out_keep = out;
        out_feat = (float4*)(out + N);
    } else if (os >= (long long)N * 64) { // features only
        out_feat = (float4*)out;
    } else {                              // keep only
        out_keep = out;
    }

    int nb = (N + 255) / 256;
    k_zero<<<512, 1024>>>();
    k_selgroups<<<1, 1024>>>();
    k_stage1<<<nb, 256>>>(coords, N, npb);
    k_coarse<<<NB, 1024>>>();
    k_finecnt<<<nb, 256>>>(N, npb);
    k_finescan<<<NB * 4, 1024>>>();
    k_qcalc<<<1, 32>>>();
    long long tot = (long long)N * 16;
    k_final<<<(int)((tot + 255) / 256), 256>>>(feat, out_keep, out_feat, N, npb);
}

// round 5
// speedup vs baseline: 1.2087x; 1.2087x over previous
#include <cuda_runtime.h>
#include <stdint.h>
#include <math.h>

// ============================================================================
// RadialMasking — bit-exact JAX reproduction (fdlibm atan2f, confirmed R4).
//  R5 perf: warp-shuffle scans + cooperative bucket walk in k_coarse/k_finescan
//  (38.7us latency-bound -> ~2us each); k_zero+k_selgroups fused; k_qcalc
//  folded into k_final; keep1 packed into dist sign bit.
// ============================================================================

#define NMAX 1600000
#define NB 8

__device__ unsigned int  g_histall[8 + NB * 4][65536]; // [0..7] coarse, [8+b*4+s] fine
__device__ unsigned int  g_distk[NMAX];     // dist bits | (keep1 << 31)
__device__ unsigned int  g_selbits[96];
__device__ unsigned int  g_m[NB];
__device__ int           g_bucket[NB][4];
__device__ int           g_rankin[NB][4];
__device__ float         g_w[NB][4];        // lw(q1), hw(q1), lw(q2), hw(q2)
__device__ float         g_selval[NB][4];   // order-stat values for the 4 ranks

// ---------------- fdlibm flt-32 atanf / atan2f ------------------------------
__device__ __forceinline__ float fd_atanf(float x) {
    const float atanhi[4] = {4.6364760399e-01f, 7.8539812565e-01f,
                             9.8279368877e-01f, 1.5707962513e+00f};
    const float atanlo[4] = {5.0121582440e-09f, 3.7748947079e-08f,
                             3.4473217170e-08f, 7.5497894159e-08f};
    const float aT0 =  3.3333328366e-01f;
    const float aT1 = -1.9999158382e-01f;
    const float aT2 =  1.4253635705e-01f;
    const float aT3 = -1.0648017377e-01f;
    const float aT4 =  6.1687607318e-02f;
    unsigned ix = __float_as_uint(x);
    unsigned sign = ix >> 31;
    ix &= 0x7fffffffu;
    int id;
    if (ix >= 0x4c800000u) {                 // |x| >= 2^26
        float z = atanhi[3];
        return sign ? -z : z;
    }
    if (ix < 0x3ee00000u) {                  // |x| < 0.4375
        if (ix < 0x39800000u) return x;      // |x| < 2^-12
        id = -1;
    } else {
        x = fabsf(x);
        if (ix < 0x3f980000u) {
            if (ix < 0x3f300000u) {
                id = 0;
                x = __fdiv_rn(__fsub_rn(__fadd_rn(x, x), 1.0f), __fadd_rn(2.0f, x));
            } else {
                id = 1;
                x = __fdiv_rn(__fsub_rn(x, 1.0f), __fadd_rn(x, 1.0f));
            }
        } else {
            if (ix < 0x401c0000u) {
                id = 2;
                x = __fdiv_rn(__fsub_rn(x, 1.5f), __fadd_rn(1.0f, __fmul_rn(1.5f, x)));
            } else {
                id = 3;
                x = __fdiv_rn(-1.0f, x);
            }
        }
    }
    float z = __fmul_rn(x, x);
    float w = __fmul_rn(z, z);
    float s1 = __fmul_rn(z, __fadd_rn(aT0, __fmul_rn(w, __fadd_rn(aT2, __fmul_rn(w, aT4)))));
    float s2 = __fmul_rn(w, __fadd_rn(aT1, __fmul_rn(w, aT3)));
    if (id < 0)
        return __fsub_rn(x, __fmul_rn(x, __fadd_rn(s1, s2)));
    z = __fsub_rn(atanhi[id],
                  __fsub_rn(__fsub_rn(__fmul_rn(x, __fadd_rn(s1, s2)), atanlo[id]), x));
    return sign ? -z : z;
}

__device__ __forceinline__ float fd_atan2f(float y, float x) {
    const float pi    = 3.1415927410e+00f;
    const float pi_lo = -8.7422776573e-08f;
    const float pio2  = 1.5707963705e+00f;
    unsigned hx = __float_as_uint(x), hy = __float_as_uint(y);
    if (hx == 0x3f800000u) return fd_atanf(y);
    unsigned m = ((hy >> 31) & 1u) | ((hx >> 30) & 2u);
    unsigned ix = hx & 0x7fffffffu, iy = hy & 0x7fffffffu;
    if (iy == 0u) {
        switch (m) {
        case 0: case 1: return y;
        case 2: return pi;
        default: return -pi;
        }
    }
    if (ix == 0u) return (m & 1u) ? -pio2 : pio2;
    if (ix + (26u << 23) < iy) return (m & 1u) ? -pio2 : pio2;
    float z;
    if ((m & 2u) && iy + (26u << 23) < ix)
        z = 0.0f;
    else
        z = fd_atanf(fabsf(__fdiv_rn(y, x)));
    switch (m) {
    case 0: return z;
    case 1: return -z;
    case 2: return __fsub_rn(pi, __fsub_rn(z, pi_lo));
    default: return __fsub_rn(__fsub_rn(z, pi_lo), pi);
    }
}

// ---------------- Threefry-2x32 ----------------------------------------------
__device__ __forceinline__ void tf_round(unsigned& x0, unsigned& x1, int r) {
    x0 += x1;
    x1 = __funnelshift_l(x1, x1, r);
    x1 ^= x0;
}

__device__ __forceinline__ uint2 tf2x32(unsigned k0, unsigned k1, unsigned x0, unsigned x1) {
    unsigned k2 = k0 ^ k1 ^ 0x1BD11BDAu;
    x0 += k0; x1 += k1;
    tf_round(x0, x1, 13); tf_round(x0, x1, 15); tf_round(x0, x1, 26); tf_round(x0, x1, 6);
    x0 += k1; x1 += k2 + 1u;
    tf_round(x0, x1, 17); tf_round(x0, x1, 29); tf_round(x0, x1, 16); tf_round(x0, x1, 24);
    x0 += k2; x1 += k0 + 2u;
    tf_round(x0, x1, 13); tf_round(x0, x1, 15); tf_round(x0, x1, 26); tf_round(x0, x1, 6);
    x0 += k0; x1 += k1 + 3u;
    tf_round(x0, x1, 17); tf_round(x0, x1, 29); tf_round(x0, x1, 16); tf_round(x0, x1, 24);
    x0 += k1; x1 += k2 + 4u;
    tf_round(x0, x1, 13); tf_round(x0, x1, 15); tf_round(x0, x1, 26); tf_round(x0, x1, 6);
    x0 += k2; x1 += k0 + 5u;
    return make_uint2(x0, x1);
}

__device__ __forceinline__ float bits_to_unit(unsigned bits) {
    return __fadd_rn(__uint_as_float((bits >> 9) | 0x3f800000u), -1.0f);
}

__device__ __forceinline__ unsigned warp_iscan(unsigned v, int lane) {
#pragma unroll
    for (int o = 1; o < 32; o <<= 1) {
        unsigned n = __shfl_up_sync(0xffffffffu, v, o);
        if (lane >= o) v += n;
    }
    return v;
}

// ---------------- k_init: zero hists (blocks 0..159) + selgroups (block 160) -
__global__ void k_init() {
    if (blockIdx.x < 160) {
        uint4* p = (uint4*)&g_histall[0][0];
        unsigned base = blockIdx.x * 4096u + threadIdx.x;
#pragma unroll
        for (int i = 0; i < 4; i++)
            p[base + i * 1024u] = make_uint4(0u, 0u, 0u, 0u);
    } else {
        int t = threadIdx.x;
        if (t < 96) g_selbits[t] = 0u;
        __syncthreads();
        uint2 kg = tf2x32(0u, 42u, 0u, 0u);
        for (int i = t; i < NB * 360; i += 1024) {
            uint2 r = tf2x32(kg.x, kg.y, 0u, (unsigned)i);
            if (bits_to_unit(r.x ^ r.y) < 0.2f)
                atomicOr(&g_selbits[i >> 5], 1u << (i & 31));
        }
    }
}

// ---------------- k_stage1 ---------------------------------------------------
__global__ void k_stage1(const int4* __restrict__ coords, int N, int npb) {
    int p = blockIdx.x * blockDim.x + threadIdx.x;
    if (p >= N) return;
    int4 c = coords[p];  // (b, z, y, x)
    float xm = __fadd_rn(__fmul_rn((float)c.w, 0.1f), -70.0f);
    float ym = __fadd_rn(__fmul_rn((float)c.z, 0.1f), -40.0f);
    float th = fd_atan2f(ym, xm);
    float td = __fmul_rn(th, 57.29577951308232f);
    float tm = (td < 0.0f) ? __fadd_rn(td, 360.0f) : td;
    int grp = (int)tm;
    grp = min(max(grp, 0), 359);
    int b = p / npb;
    int bitidx = b * 360 + grp;
    unsigned keep1 = (g_selbits[bitidx >> 5] >> (bitidx & 31)) & 1u;
    float d2 = __fadd_rn(__fmul_rn(xm, xm), __fmul_rn(ym, ym));
    float dist = __fsqrt_rn(d2);
    unsigned db = __float_as_uint(dist);
    if (keep1) {
        atomicAdd(&g_histall[b][db >> 16], 1u);
        db |= 0x80000000u;
    }
    g_distk[p] = db;
}

// ---------------- k_coarse: warp-scan + cooperative rank walk ---------------
__global__ void k_coarse() {
    int b = blockIdx.x;
    int t = threadIdx.x, lane = t & 31, warp = t >> 5;
    const unsigned* hist = g_histall[b];
    const uint4* h4 = (const uint4*)hist;
    unsigned psum = 0;
#pragma unroll
    for (int i = 0; i < 16; i++) {
        uint4 q = h4[t * 16 + i];
        psum += q.x + q.y + q.z + q.w;
    }
    unsigned incl = warp_iscan(psum, lane);
    __shared__ unsigned wtot[32], wpre[32];
    __shared__ unsigned s_m;
    __shared__ unsigned s_r[4];
    __shared__ int      s_seg[4];
    __shared__ unsigned s_base[4];
    if (lane == 31) wtot[warp] = incl;
    __syncthreads();
    if (warp == 0) {
        unsigned v = wtot[lane];
        unsigned iv = warp_iscan(v, lane);
        wpre[lane] = iv - v;
        if (lane == 31) s_m = iv;
    }
    __syncthreads();
    unsigned m = s_m;
    if (t == 0) {
        g_m[b] = m;
        // JAX nanquantile (squash_nans, 'linear'), f32:
        float mf  = (float)m;
        float cm1 = __fsub_rn(mf, 1.0f);
        const float qv[2] = {0.33f, 0.67f};
#pragma unroll
        for (int j = 0; j < 2; j++) {
            float qidx = __fmul_rn(qv[j], cm1);
            float lo = floorf(qidx), hi = ceilf(qidx);
            float hw = __fsub_rn(qidx, lo);
            float lw = __fsub_rn(1.0f, hw);
            float loc = fmaxf(0.0f, fminf(lo, cm1));
            float hic = fmaxf(0.0f, fminf(hi, cm1));
            s_r[j * 2]     = (unsigned)(int)loc;
            s_r[j * 2 + 1] = (unsigned)(int)hic;
            g_w[b][j * 2]     = lw;
            g_w[b][j * 2 + 1] = hw;
        }
    }
    __syncthreads();
    if (m != 0) {
        unsigned excl = wpre[warp] + incl - psum;
#pragma unroll
        for (int s = 0; s < 4; s++) {
            unsigned r = s_r[s];
            if (r >= excl && r < excl + psum) { s_seg[s] = t; s_base[s] = excl; }
        }
    }
    __syncthreads();
    if (warp < 4) {
        int s = warp;
        if (m == 0) {
            if (lane == 0) { g_bucket[b][s] = -1; g_rankin[b][s] = 0; }
        } else {
            int seg = s_seg[s];
            unsigned rrem = s_r[s] - s_base[s];
            unsigned a0 = hist[seg * 64 + 2 * lane];
            unsigned a1 = hist[seg * 64 + 2 * lane + 1];
            unsigned pr = a0 + a1;
            unsigned pincl = warp_iscan(pr, lane);
            unsigned pexcl = pincl - pr;
            if (rrem >= pexcl && rrem < pincl) {
                unsigned local = rrem - pexcl;
                int bin; unsigned rk;
                if (local < a0) { bin = seg * 64 + 2 * lane;     rk = local; }
                else            { bin = seg * 64 + 2 * lane + 1; rk = local - a0; }
                g_bucket[b][s] = bin;
                g_rankin[b][s] = (int)rk;
            }
        }
    }
}

// ---------------- k_finecnt --------------------------------------------------
__global__ void k_finecnt(int N, int npb) {
    int p = blockIdx.x * blockDim.x + threadIdx.x;
    if (p >= N) return;
    unsigned u = g_distk[p];
    if (!(u & 0x80000000u)) return;
    unsigned bits = u & 0x7fffffffu;
    int b = p / npb;
    int coarse = (int)(bits >> 16);
    unsigned fbin = bits & 0xFFFFu;
#pragma unroll
    for (int s = 0; s < 4; s++)
        if (g_bucket[b][s] == coarse)
            atomicAdd(&g_histall[8 + b * 4 + s][fbin], 1u);
}

// ---------------- k_finescan: same warp-scan structure, 1 rank per block ----
__global__ void k_finescan() {
    int b = blockIdx.x >> 2, s = blockIdx.x & 3;
    int bucket = g_bucket[b][s];
    int t = threadIdx.x, lane = t & 31, warp = t >> 5;
    if (bucket < 0) {
        if (t == 0) g_selval[b][s] = __int_as_float(0x7fc00000);
        return;
    }
    const unsigned* hist = g_histall[8 + b * 4 + s];
    const uint4* h4 = (const uint4*)hist;
    unsigned psum = 0;
#pragma unroll
    for (int i = 0; i < 16; i++) {
        uint4 q = h4[t * 16 + i];
        psum += q.x + q.y + q.z + q.w;
    }
    unsigned incl = warp_iscan(psum, lane);
    __shared__ unsigned wtot[32], wpre[32];
    __shared__ int      s_seg;
    __shared__ unsigned s_base;
    if (lane == 31) wtot[warp] = incl;
    __syncthreads();
    if (warp == 0) {
        unsigned v = wtot[lane];
        unsigned iv = warp_iscan(v, lane);
        wpre[lane] = iv - v;
    }
    __syncthreads();
    unsigned r = (unsigned)g_rankin[b][s];
    unsigned excl = wpre[warp] + incl - psum;
    if (r >= excl && r < excl + psum) { s_seg = t; s_base = excl; }
    __syncthreads();
    if (warp == 0) {
        int seg = s_seg;
        unsigned rrem = r - s_base;
        unsigned a0 = hist[seg * 64 + 2 * lane];
        unsigned a1 = hist[seg * 64 + 2 * lane + 1];
        unsigned pr = a0 + a1;
        unsigned pincl = warp_iscan(pr, lane);
        unsigned pexcl = pincl - pr;
        if (rrem >= pexcl && rrem < pincl) {
            unsigned local = rrem - pexcl;
            int bin = (local < a0) ? (seg * 64 + 2 * lane) : (seg * 64 + 2 * lane + 1);
            g_selval[b][s] = __uint_as_float(((unsigned)bucket << 16) | (unsigned)bin);
        }
    }
}

// ---------------- k_final ----------------------------------------------------
// 16 lanes per voxel; lane0: quantile interp + Threefry + keep; shuffle bcast.
__global__ void k_final(const float4* __restrict__ feat, float* __restrict__ out_keep,
                        float4* __restrict__ out_feat, int N, int npb) {
    long long idx = (long long)blockIdx.x * blockDim.x + threadIdx.x;
    int v = (int)(idx >> 4);
    int lane16 = (int)(idx & 15);
    bool active = (v < N);
    int vv = active ? v : (N - 1);
    float kf = 0.0f;
    if (lane16 == 0) {
        unsigned u = g_distk[vv];
        unsigned keep1 = u >> 31;
        float dist = __uint_as_float(u & 0x7fffffffu);
        int b = vv / npb;
        float q1, q2;
        if (g_m[b] == 0) {
            q1 = q2 = __int_as_float(0x7fc00000);
        } else {
            q1 = __fadd_rn(__fmul_rn(g_selval[b][0], g_w[b][0]),
                           __fmul_rn(g_selval[b][1], g_w[b][1]));
            q2 = __fadd_rn(__fmul_rn(g_selval[b][2], g_w[b][2]),
                           __fmul_rn(g_selval[b][3], g_w[b][3]));
        }
        float prob = (dist < q1) ? 0.48f : ((dist < q2) ? 0.8f : 0.95f);
        uint2 kv = tf2x32(0u, 42u, 0u, 1u);
        uint2 r = tf2x32(kv.x, kv.y, 0u, (unsigned)vv);
        float uu = bits_to_unit(r.x ^ r.y);
        bool keep = keep1 && (uu >= prob);
        kf = keep ? 1.0f : 0.0f;
        if (active && out_keep != nullptr) out_keep[vv] = kf;
    }
    int lw = threadIdx.x & 31;
    kf = __shfl_sync(0xffffffffu, kf, lw & ~15);
    if (active && out_feat != nullptr) {
        size_t off = (size_t)vv * 16 + lane16;
        if (kf != 0.0f) {
            out_feat[off] = feat[off];
        } else {
            out_feat[off] = make_float4(0.0f, 0.0f, 0.0f, 0.0f);
        }
    }
}

// ---------------- launcher ----------------------------------------------------
extern "C" void kernel_launch(void* const* d_in, const int* in_sizes, int n_in,
                              void* d_out, int out_size) {
    int i_coords = 0, i_feat = 1;
    if (n_in >= 2 && in_sizes[0] > in_sizes[1]) { i_coords = 1; i_feat = 0; }
    const int4*   coords = (const int4*)d_in[i_coords];
    const float4* feat   = (const float4*)d_in[i_feat];
    int N = in_sizes[i_coords] / 4;
    int npb = N / NB;

    float*  out      = (float*)d_out;
    float*  out_keep = nullptr;
    float4* out_feat = nullptr;
    long long os = (long long)out_size;
    if (os >= (long long)N * 65) {
        out_keep = out;
        out_feat = (float4*)(out + N);
    } else if (os >= (long long)N * 64) {
        out_feat = (float4*)out;
    } else {
        out_keep = out;
    }

    int nb = (N + 255) / 256;
    k_init<<<161, 1024>>>();
    k_stage1<<<nb, 256>>>(coords, N, npb);
    k_coarse<<<NB, 1024>>>();
    k_finecnt<<<nb, 256>>>(N, npb);
    k_finescan<<<NB * 4, 1024>>>();
    long long tot = (long long)N * 16;
    k_final<<<(int)((tot + 255) / 256), 256>>>(feat, out_keep, out_feat, N, npb);
}

// round 6
// speedup vs baseline: 1.5571x; 1.2882x over previous
#include <cuda_runtime.h>
#include <stdint.h>
#include <math.h>

// ============================================================================
// RadialMasking — bit-exact JAX reproduction (fdlibm atan2f, confirmed R4).
//  R6 perf: keep-mask computation moved out of k_final into k_keep (all lanes
//  active; k_final had Threefry on 2/32 lanes = ~60us warp-serialized ALU).
//  k_final is now a pure bit-gated copy. Magic-mul division for p/npb.
// ============================================================================

#define NMAX 1600000
#define NB 8

__device__ unsigned int  g_histall[8 + NB * 4][65536]; // [0..7] coarse, [8+b*4+s] fine
__device__ unsigned int  g_distk[NMAX];       // dist bits | (keep1 << 31)
__device__ unsigned int  g_keepbits[NMAX / 32 + 1];
__device__ unsigned int  g_selbits[96];
__device__ unsigned int  g_m[NB];
__device__ int           g_bucket[NB][4];
__device__ int           g_rankin[NB][4];
__device__ float         g_w[NB][4];          // lw(q1), hw(q1), lw(q2), hw(q2)
__device__ float         g_selval[NB][4];     // order-stat values for the 4 ranks

// ---------------- fdlibm flt-32 atanf / atan2f ------------------------------
__device__ __forceinline__ float fd_atanf(float x) {
    const float atanhi[4] = {4.6364760399e-01f, 7.8539812565e-01f,
                             9.8279368877e-01f, 1.5707962513e+00f};
    const float atanlo[4] = {5.0121582440e-09f, 3.7748947079e-08f,
                             3.4473217170e-08f, 7.5497894159e-08f};
    const float aT0 =  3.3333328366e-01f;
    const float aT1 = -1.9999158382e-01f;
    const float aT2 =  1.4253635705e-01f;
    const float aT3 = -1.0648017377e-01f;
    const float aT4 =  6.1687607318e-02f;
    unsigned ix = __float_as_uint(x);
    unsigned sign = ix >> 31;
    ix &= 0x7fffffffu;
    int id;
    if (ix >= 0x4c800000u) {
        float z = atanhi[3];
        return sign ? -z : z;
    }
    if (ix < 0x3ee00000u) {
        if (ix < 0x39800000u) return x;
        id = -1;
    } else {
        x = fabsf(x);
        if (ix < 0x3f980000u) {
            if (ix < 0x3f300000u) {
                id = 0;
                x = __fdiv_rn(__fsub_rn(__fadd_rn(x, x), 1.0f), __fadd_rn(2.0f, x));
            } else {
                id = 1;
                x = __fdiv_rn(__fsub_rn(x, 1.0f), __fadd_rn(x, 1.0f));
            }
        } else {
            if (ix < 0x401c0000u) {
                id = 2;
                x = __fdiv_rn(__fsub_rn(x, 1.5f), __fadd_rn(1.0f, __fmul_rn(1.5f, x)));
            } else {
                id = 3;
                x = __fdiv_rn(-1.0f, x);
            }
        }
    }
    float z = __fmul_rn(x, x);
    float w = __fmul_rn(z, z);
    float s1 = __fmul_rn(z, __fadd_rn(aT0, __fmul_rn(w, __fadd_rn(aT2, __fmul_rn(w, aT4)))));
    float s2 = __fmul_rn(w, __fadd_rn(aT1, __fmul_rn(w, aT3)));
    if (id < 0)
        return __fsub_rn(x, __fmul_rn(x, __fadd_rn(s1, s2)));
    z = __fsub_rn(atanhi[id],
                  __fsub_rn(__fsub_rn(__fmul_rn(x, __fadd_rn(s1, s2)), atanlo[id]), x));
    return sign ? -z : z;
}

__device__ __forceinline__ float fd_atan2f(float y, float x) {
    const float pi    = 3.1415927410e+00f;
    const float pi_lo = -8.7422776573e-08f;
    const float pio2  = 1.5707963705e+00f;
    unsigned hx = __float_as_uint(x), hy = __float_as_uint(y);
    if (hx == 0x3f800000u) return fd_atanf(y);
    unsigned m = ((hy >> 31) & 1u) | ((hx >> 30) & 2u);
    unsigned ix = hx & 0x7fffffffu, iy = hy & 0x7fffffffu;
    if (iy == 0u) {
        switch (m) {
        case 0: case 1: return y;
        case 2: return pi;
        default: return -pi;
        }
    }
    if (ix == 0u) return (m & 1u) ? -pio2 : pio2;
    if (ix + (26u << 23) < iy) return (m & 1u) ? -pio2 : pio2;
    float z;
    if ((m & 2u) && iy + (26u << 23) < ix)
        z = 0.0f;
    else
        z = fd_atanf(fabsf(__fdiv_rn(y, x)));
    switch (m) {
    case 0: return z;
    case 1: return -z;
    case 2: return __fsub_rn(pi, __fsub_rn(z, pi_lo));
    default: return __fsub_rn(__fsub_rn(z, pi_lo), pi);
    }
}

// ---------------- Threefry-2x32 ----------------------------------------------
__device__ __forceinline__ void tf_round(unsigned& x0, unsigned& x1, int r) {
    x0 += x1;
    x1 = __funnelshift_l(x1, x1, r);
    x1 ^= x0;
}

__device__ __forceinline__ uint2 tf2x32(unsigned k0, unsigned k1, unsigned x0, unsigned x1) {
    unsigned k2 = k0 ^ k1 ^ 0x1BD11BDAu;
    x0 += k0; x1 += k1;
    tf_round(x0, x1, 13); tf_round(x0, x1, 15); tf_round(x0, x1, 26); tf_round(x0, x1, 6);
    x0 += k1; x1 += k2 + 1u;
    tf_round(x0, x1, 17); tf_round(x0, x1, 29); tf_round(x0, x1, 16); tf_round(x0, x1, 24);
    x0 += k2; x1 += k0 + 2u;
    tf_round(x0, x1, 13); tf_round(x0, x1, 15); tf_round(x0, x1, 26); tf_round(x0, x1, 6);
    x0 += k0; x1 += k1 + 3u;
    tf_round(x0, x1, 17); tf_round(x0, x1, 29); tf_round(x0, x1, 16); tf_round(x0, x1, 24);
    x0 += k1; x1 += k2 + 4u;
    tf_round(x0, x1, 13); tf_round(x0, x1, 15); tf_round(x0, x1, 26); tf_round(x0, x1, 6);
    x0 += k2; x1 += k0 + 5u;
    return make_uint2(x0, x1);
}

__device__ __forceinline__ float bits_to_unit(unsigned bits) {
    return __fadd_rn(__uint_as_float((bits >> 9) | 0x3f800000u), -1.0f);
}

__device__ __forceinline__ unsigned warp_iscan(unsigned v, int lane) {
#pragma unroll
    for (int o = 1; o < 32; o <<= 1) {
        unsigned n = __shfl_up_sync(0xffffffffu, v, o);
        if (lane >= o) v += n;
    }
    return v;
}

// exact p/npb for p < 2^24 via host-computed magic M = floor(2^42/npb)+1
__device__ __forceinline__ int div_npb(int p, unsigned long long magic) {
    return (int)(((unsigned long long)(unsigned)p * magic) >> 42);
}

// ---------------- k_init: zero hists (blocks 0..159) + selgroups (block 160) -
__global__ void k_init() {
    if (blockIdx.x < 160) {
        uint4* p = (uint4*)&g_histall[0][0];
        unsigned base = blockIdx.x * 4096u + threadIdx.x;
#pragma unroll
        for (int i = 0; i < 4; i++)
            p[base + i * 1024u] = make_uint4(0u, 0u, 0u, 0u);
    } else {
        int t = threadIdx.x;
        if (t < 96) g_selbits[t] = 0u;
        __syncthreads();
        uint2 kg = tf2x32(0u, 42u, 0u, 0u);
        for (int i = t; i < NB * 360; i += 1024) {
            uint2 r = tf2x32(kg.x, kg.y, 0u, (unsigned)i);
            if (bits_to_unit(r.x ^ r.y) < 0.2f)
                atomicOr(&g_selbits[i >> 5], 1u << (i & 31));
        }
    }
}

// ---------------- k_stage1 ---------------------------------------------------
__global__ void k_stage1(const int4* __restrict__ coords, int N, int npb) {
    int p = blockIdx.x * blockDim.x + threadIdx.x;
    if (p >= N) return;
    int4 c = coords[p];  // (b, z, y, x)
    float xm = __fadd_rn(__fmul_rn((float)c.w, 0.1f), -70.0f);
    float ym = __fadd_rn(__fmul_rn((float)c.z, 0.1f), -40.0f);
    float th = fd_atan2f(ym, xm);
    float td = __fmul_rn(th, 57.29577951308232f);
    float tm = (td < 0.0f) ? __fadd_rn(td, 360.0f) : td;
    int grp = (int)tm;
    grp = min(max(grp, 0), 359);
    int b = c.x;  // batch id directly from coords
    int bitidx = b * 360 + grp;
    unsigned keep1 = (g_selbits[bitidx >> 5] >> (bitidx & 31)) & 1u;
    float d2 = __fadd_rn(__fmul_rn(xm, xm), __fmul_rn(ym, ym));
    float dist = __fsqrt_rn(d2);
    unsigned db = __float_as_uint(dist);
    if (keep1) {
        atomicAdd(&g_histall[b][db >> 16], 1u);
        db |= 0x80000000u;
    }
    g_distk[p] = db;
}

// ---------------- k_coarse: warp-scan + cooperative rank walk ---------------
__global__ void k_coarse() {
    int b = blockIdx.x;
    int t = threadIdx.x, lane = t & 31, warp = t >> 5;
    const unsigned* hist = g_histall[b];
    const uint4* h4 = (const uint4*)hist;
    unsigned psum = 0;
#pragma unroll
    for (int i = 0; i < 16; i++) {
        uint4 q = h4[t * 16 + i];
        psum += q.x + q.y + q.z + q.w;
    }
    unsigned incl = warp_iscan(psum, lane);
    __shared__ unsigned wtot[32], wpre[32];
    __shared__ unsigned s_m;
    __shared__ unsigned s_r[4];
    __shared__ int      s_seg[4];
    __shared__ unsigned s_base[4];
    if (lane == 31) wtot[warp] = incl;
    __syncthreads();
    if (warp == 0) {
        unsigned v = wtot[lane];
        unsigned iv = warp_iscan(v, lane);
        wpre[lane] = iv - v;
        if (lane == 31) s_m = iv;
    }
    __syncthreads();
    unsigned m = s_m;
    if (t == 0) {
        g_m[b] = m;
        float mf  = (float)m;
        float cm1 = __fsub_rn(mf, 1.0f);
        const float qv[2] = {0.33f, 0.67f};
#pragma unroll
        for (int j = 0; j < 2; j++) {
            float qidx = __fmul_rn(qv[j], cm1);
            float lo = floorf(qidx), hi = ceilf(qidx);
            float hw = __fsub_rn(qidx, lo);
            float lw = __fsub_rn(1.0f, hw);
            float loc = fmaxf(0.0f, fminf(lo, cm1));
            float hic = fmaxf(0.0f, fminf(hi, cm1));
            s_r[j * 2]     = (unsigned)(int)loc;
            s_r[j * 2 + 1] = (unsigned)(int)hic;
            g_w[b][j * 2]     = lw;
            g_w[b][j * 2 + 1] = hw;
        }
    }
    __syncthreads();
    if (m != 0) {
        unsigned excl = wpre[warp] + incl - psum;
#pragma unroll
        for (int s = 0; s < 4; s++) {
            unsigned r = s_r[s];
            if (r >= excl && r < excl + psum) { s_seg[s] = t; s_base[s] = excl; }
        }
    }
    __syncthreads();
    if (warp < 4) {
        int s = warp;
        if (m == 0) {
            if (lane == 0) { g_bucket[b][s] = -1; g_rankin[b][s] = 0; }
        } else {
            int seg = s_seg[s];
            unsigned rrem = s_r[s] - s_base[s];
            unsigned a0 = hist[seg * 64 + 2 * lane];
            unsigned a1 = hist[seg * 64 + 2 * lane + 1];
            unsigned pr = a0 + a1;
            unsigned pincl = warp_iscan(pr, lane);
            unsigned pexcl = pincl - pr;
            if (rrem >= pexcl && rrem < pincl) {
                unsigned local = rrem - pexcl;
                int bin; unsigned rk;
                if (local < a0) { bin = seg * 64 + 2 * lane;     rk = local; }
                else            { bin = seg * 64 + 2 * lane + 1; rk = local - a0; }
                g_bucket[b][s] = bin;
                g_rankin[b][s] = (int)rk;
            }
        }
    }
}

// ---------------- k_finecnt --------------------------------------------------
__global__ void k_finecnt(int N, unsigned long long magic) {
    int p = blockIdx.x * blockDim.x + threadIdx.x;
    if (p >= N) return;
    unsigned u = g_distk[p];
    if (!(u & 0x80000000u)) return;
    unsigned bits = u & 0x7fffffffu;
    int b = div_npb(p, magic);
    int coarse = (int)(bits >> 16);
    unsigned fbin = bits & 0xFFFFu;
#pragma unroll
    for (int s = 0; s < 4; s++)
        if (g_bucket[b][s] == coarse)
            atomicAdd(&g_histall[8 + b * 4 + s][fbin], 1u);
}

// ---------------- k_finescan -------------------------------------------------
__global__ void k_finescan() {
    int b = blockIdx.x >> 2, s = blockIdx.x & 3;
    int bucket = g_bucket[b][s];
    int t = threadIdx.x, lane = t & 31, warp = t >> 5;
    if (bucket < 0) {
        if (t == 0) g_selval[b][s] = __int_as_float(0x7fc00000);
        return;
    }
    const unsigned* hist = g_histall[8 + b * 4 + s];
    const uint4* h4 = (const uint4*)hist;
    unsigned psum = 0;
#pragma unroll
    for (int i = 0; i < 16; i++) {
        uint4 q = h4[t * 16 + i];
        psum += q.x + q.y + q.z + q.w;
    }
    unsigned incl = warp_iscan(psum, lane);
    __shared__ unsigned wtot[32], wpre[32];
    __shared__ int      s_seg;
    __shared__ unsigned s_base;
    if (lane == 31) wtot[warp] = incl;
    __syncthreads();
    if (warp == 0) {
        unsigned v = wtot[lane];
        unsigned iv = warp_iscan(v, lane);
        wpre[lane] = iv - v;
    }
    __syncthreads();
    unsigned r = (unsigned)g_rankin[b][s];
    unsigned excl = wpre[warp] + incl - psum;
    if (r >= excl && r < excl + psum) { s_seg = t; s_base = excl; }
    __syncthreads();
    if (warp == 0) {
        int seg = s_seg;
        unsigned rrem = r - s_base;
        unsigned a0 = hist[seg * 64 + 2 * lane];
        unsigned a1 = hist[seg * 64 + 2 * lane + 1];
        unsigned pr = a0 + a1;
        unsigned pincl = warp_iscan(pr, lane);
        unsigned pexcl = pincl - pr;
        if (rrem >= pexcl && rrem < pincl) {
            unsigned local = rrem - pexcl;
            int bin = (local < a0) ? (seg * 64 + 2 * lane) : (seg * 64 + 2 * lane + 1);
            g_selval[b][s] = __uint_as_float(((unsigned)bucket << 16) | (unsigned)bin);
        }
    }
}

// ---------------- k_keep: per-voxel keep (all lanes active) ------------------
__global__ void k_keep(float* __restrict__ out_keep, int N, unsigned long long magic) {
    int p = blockIdx.x * blockDim.x + threadIdx.x;
    bool active = (p < N);
    int pp = active ? p : (N - 1);
    unsigned u = g_distk[pp];
    unsigned keep1 = u >> 31;
    float dist = __uint_as_float(u & 0x7fffffffu);
    int b = div_npb(pp, magic);
    float q1, q2;
    if (g_m[b] == 0) {
        q1 = q2 = __int_as_float(0x7fc00000);
    } else {
        q1 = __fadd_rn(__fmul_rn(g_selval[b][0], g_w[b][0]),
                       __fmul_rn(g_selval[b][1], g_w[b][1]));
        q2 = __fadd_rn(__fmul_rn(g_selval[b][2], g_w[b][2]),
                       __fmul_rn(g_selval[b][3], g_w[b][3]));
    }
    float prob = (dist < q1) ? 0.48f : ((dist < q2) ? 0.8f : 0.95f);
    uint2 kv = tf2x32(0u, 42u, 0u, 1u);
    uint2 r = tf2x32(kv.x, kv.y, 0u, (unsigned)pp);
    float uu = bits_to_unit(r.x ^ r.y);
    bool keep = active && keep1 && (uu >= prob);
    unsigned bal = __ballot_sync(0xffffffffu, keep);
    if ((threadIdx.x & 31) == 0) g_keepbits[p >> 5] = bal;
    if (active && out_keep != nullptr) out_keep[p] = keep ? 1.0f : 0.0f;
}

// ---------------- k_final: pure bit-gated copy -------------------------------
__global__ void k_final(const float4* __restrict__ feat, float4* __restrict__ out_feat,
                        int N) {
    long long idx = (long long)blockIdx.x * blockDim.x + threadIdx.x;
    int v = (int)(idx >> 4);
    if (v >= N) return;
    unsigned kw = g_keepbits[v >> 5];
    if ((kw >> (v & 31)) & 1u) {
        out_feat[idx] = feat[idx];
    } else {
        out_feat[idx] = make_float4(0.0f, 0.0f, 0.0f, 0.0f);
    }
}

// ---------------- launcher ----------------------------------------------------
extern "C" void kernel_launch(void* const* d_in, const int* in_sizes, int n_in,
                              void* d_out, int out_size) {
    int i_coords = 0, i_feat = 1;
    if (n_in >= 2 && in_sizes[0] > in_sizes[1]) { i_coords = 1; i_feat = 0; }
    const int4*   coords = (const int4*)d_in[i_coords];
    const float4* feat   = (const float4*)d_in[i_feat];
    int N = in_sizes[i_coords] / 4;
    int npb = N / NB;
    unsigned long long magic = (4398046511104ULL / (unsigned long long)npb) + 1ULL;

    float*  out      = (float*)d_out;
    float*  out_keep = nullptr;
    float4* out_feat = nullptr;
    long long os = (long long)out_size;
    if (os >= (long long)N * 65) {
        out_keep = out;
        out_feat = (float4*)(out + N);
    } else if (os >= (long long)N * 64) {
        out_feat = (float4*)out;
    } else {
        out_keep = out;
    }

    int nb = (N + 255) / 256;
    k_init<<<161, 1024>>>();
    k_stage1<<<nb, 256>>>(coords, N, npb);
    k_coarse<<<NB, 1024>>>();
    k_finecnt<<<nb, 256>>>(N, magic);
    k_finescan<<<NB * 4, 1024>>>();
    k_keep<<<nb, 256>>>(out_keep, N, magic);
    if (out_feat != nullptr) {
        long long tot = (long long)N * 16;
        k_final<<<(int)((tot + 255) / 256), 256>>>(feat, out_feat, N);
    }
}